// round 6
// baseline (speedup 1.0000x reference)
#include <cuda_runtime.h>
#include <stdint.h>

#define NU 8000
#define NI 4000
#define NN 12000
#define NE 300000
#define ED 64
#define WPR (NN / 32)              // words per bitmask row = 375
#define MASK_WORDS (NN * WPR)      // 4,500,000 words = 18 MB

// ---- static device scratch (no allocations allowed) ----
__device__ unsigned int g_mask[MASK_WORDS];
__device__ int   g_deg[NN];
__device__ int   g_rowptr[NN + 1];
__device__ float g_dsqrtinv[NN];
__device__ int   g_col[2 * NE];
__device__ float g_val[2 * NE];
__device__ float g_bufA[NN * ED];
__device__ float g_bufB[NN * ED];
__device__ int   g_is64;           // 1 if edge_index is int64

// ---------------- detect edge_index dtype ----------------
// int64 little-endian values < 12000 => every odd 32-bit word is 0.
// int32 random values in [0,12000): probability all 128 odd words are 0 is ~0.
__global__ void lg_detect_kernel(const unsigned int* __restrict__ ei_raw) {
    if (threadIdx.x == 0) {
        int all_zero = 1;
        for (int k = 0; k < 128; ++k) {
            if (ei_raw[2 * k + 1] != 0u) { all_zero = 0; break; }
        }
        g_is64 = all_zero;
    }
}

// ---------------- clear mask + degrees ----------------
__global__ void lg_clear_kernel() {
    int idx = blockIdx.x * blockDim.x + threadIdx.x;
    int stride = gridDim.x * blockDim.x;
    for (int w = idx; w < MASK_WORDS; w += stride) g_mask[w] = 0u;
    for (int w = idx; w < NN; w += stride) g_deg[w] = 0;
}

// ---------------- mark edges (dedup via bitmask), count degrees ----------------
__global__ void lg_mark_kernel(const int* __restrict__ ei) {
    int t = blockIdx.x * blockDim.x + threadIdx.x;
    if (t >= 2 * NE) return;
    int e = t < NE ? t : t - NE;
    int u, v;
    if (g_is64) {
        // int64 storage: element k lives at 32-bit word 2k (low half)
        u = ei[2 * e];
        v = ei[2 * (NE + e)];
    } else {
        u = ei[e];          // row 0: src
        v = ei[NE + e];     // row 1: dst
    }
    int i, j;
    if (t < NE) { i = u; j = v; } else { i = v; j = u; }
    size_t bit = (size_t)i * NN + (size_t)j;
    unsigned int bm = 1u << (bit & 31);
    unsigned int old = atomicOr(&g_mask[bit >> 5], bm);
    if (!(old & bm)) atomicAdd(&g_deg[i], 1);
}

// ---------------- prefix scan of degrees -> rowptr, plus rsqrt degrees ----------------
__global__ void lg_scan_kernel() {
    __shared__ int sh[1024];
    int carry = 0;
    for (int base = 0; base < NN; base += 1024) {
        int idx = base + (int)threadIdx.x;
        int v = (idx < NN) ? g_deg[idx] : 0;
        if (idx < NN) {
            int d = v > 1 ? v : 1;
            g_dsqrtinv[idx] = rsqrtf((float)d);
        }
        sh[threadIdx.x] = v;
        __syncthreads();
        // Hillis-Steele inclusive scan
        for (int off = 1; off < 1024; off <<= 1) {
            int t = (threadIdx.x >= (unsigned)off) ? sh[threadIdx.x - off] : 0;
            __syncthreads();
            sh[threadIdx.x] += t;
            __syncthreads();
        }
        if (idx < NN) g_rowptr[idx + 1] = carry + sh[threadIdx.x];
        carry += sh[1023];
        __syncthreads();
    }
    if (threadIdx.x == 0) g_rowptr[0] = 0;
}

// ---------------- fill CSR (warp per row, deterministic sorted columns) ----------------
__global__ void lg_fill_kernel() {
    int warp = (blockIdx.x * blockDim.x + threadIdx.x) >> 5;
    int lane = threadIdx.x & 31;
    if (warp >= NN) return;
    const int i = warp;
    const unsigned int* row = g_mask + (size_t)i * WPR;
    int pos = g_rowptr[i];
    float di = g_dsqrtinv[i];
    for (int c = 0; c < WPR; c += 32) {
        int widx = c + lane;
        unsigned int w = (widx < WPR) ? row[widx] : 0u;
        int cnt = __popc(w);
        // warp inclusive scan of counts
        int inc = cnt;
        #pragma unroll
        for (int s = 1; s < 32; s <<= 1) {
            int t = __shfl_up_sync(0xffffffffu, inc, s);
            if (lane >= s) inc += t;
        }
        int total = __shfl_sync(0xffffffffu, inc, 31);
        int p = pos + inc - cnt;   // exclusive offset
        int jbase = widx * 32;
        while (w) {
            int b = __ffs(w) - 1;
            w &= w - 1;
            int j = jbase + b;
            g_col[p] = j;
            g_val[p] = di * g_dsqrtinv[j];
            p++;
        }
        pos += total;
    }
}

// ---------------- init: concat embeddings into bufA and accumulator (d_out) ----------------
__global__ void lg_init_kernel(const float* __restrict__ uemb,
                               const float* __restrict__ iemb,
                               float* __restrict__ out) {
    int idx = blockIdx.x * blockDim.x + threadIdx.x;
    if (idx >= NN * ED) return;
    float v;
    if (idx < NU * ED) v = uemb[idx];
    else               v = iemb[idx - NU * ED];
    g_bufA[idx] = v;
    out[idx] = v;
}

// ---------------- SpMM: xout[i,:] = sum_j w_ij * xin[j,:]; accum += xout; scale last ----
// flip=0: read g_bufA, write g_bufB.  flip=1: read g_bufB, write g_bufA.
// Device-symbol pointers are resolved IN DEVICE CODE (host-side &g_bufX is the
// host shadow address — on GB300 ATS makes that silently readable => zeros).
__global__ void __launch_bounds__(ED) lg_spmm_kernel(int flip,
                                                     float* __restrict__ accum,
                                                     float scale) {
    const float* __restrict__ xin = flip ? g_bufB : g_bufA;
    float* __restrict__ xout      = flip ? g_bufA : g_bufB;
    int i = blockIdx.x;
    int d = threadIdx.x;  // 0..63
    int s = g_rowptr[i];
    int e = g_rowptr[i + 1];
    float acc = 0.0f;
    int p = s;
    for (; p + 4 <= e; p += 4) {
        int j0 = g_col[p + 0]; float w0 = g_val[p + 0];
        int j1 = g_col[p + 1]; float w1 = g_val[p + 1];
        int j2 = g_col[p + 2]; float w2 = g_val[p + 2];
        int j3 = g_col[p + 3]; float w3 = g_val[p + 3];
        float x0 = __ldg(&xin[(size_t)j0 * ED + d]);
        float x1 = __ldg(&xin[(size_t)j1 * ED + d]);
        float x2 = __ldg(&xin[(size_t)j2 * ED + d]);
        float x3 = __ldg(&xin[(size_t)j3 * ED + d]);
        acc += w0 * x0 + w1 * x1 + w2 * x2 + w3 * x3;
    }
    for (; p < e; ++p) {
        acc += g_val[p] * __ldg(&xin[(size_t)g_col[p] * ED + d]);
    }
    size_t o = (size_t)i * ED + d;
    xout[o] = acc;
    accum[o] = (accum[o] + acc) * scale;
}

extern "C" void kernel_launch(void* const* d_in, const int* in_sizes, int n_in,
                              void* d_out, int out_size) {
    const int*   edge_index = (const int*)d_in[0];   // (2, NE) int32 (or int64; detected)
    const float* user_emb   = (const float*)d_in[1]; // (NU, 64)
    const float* item_emb   = (const float*)d_in[2]; // (NI, 64)
    float* out = (float*)d_out;                       // (NN, 64) concat(users, items)

    (void)in_sizes; (void)n_in; (void)out_size;

    // 0. detect int32 vs int64 edge_index
    lg_detect_kernel<<<1, 32>>>((const unsigned int*)d_in[0]);
    // 1. clear dedup bitmask + degrees
    lg_clear_kernel<<<4096, 256>>>();
    // 2. mark both directions, dedup, count degrees
    lg_mark_kernel<<<(2 * NE + 255) / 256, 256>>>(edge_index);
    // 3. rowptr prefix scan + rsqrt(deg)
    lg_scan_kernel<<<1, 1024>>>();
    // 4. deterministic CSR fill (sorted columns)
    lg_fill_kernel<<<(NN * 32 + 127) / 128, 128>>>();
    // 5. init X0 and accumulator (= layer-0 term)
    lg_init_kernel<<<(NN * ED + 255) / 256, 256>>>(user_emb, item_emb, out);
    // 6. three propagation layers; accumulate; mean(4 layers) on the last
    lg_spmm_kernel<<<NN, ED>>>(0, out, 1.0f);
    lg_spmm_kernel<<<NN, ED>>>(1, out, 1.0f);
    lg_spmm_kernel<<<NN, ED>>>(0, out, 0.25f);
}

// round 10
// speedup vs baseline: 1.6983x; 1.6983x over previous
#include <cuda_runtime.h>
#include <stdint.h>

#define NU 8000
#define NI 4000
#define NN 12000
#define NE 300000
#define ED 64
#define WPR (NN / 32)              // words per bitmask row = 375
#define MASK_WORDS (NN * WPR)      // 4,500,000 words = 18 MB

// ---- static device scratch (no allocations allowed) ----
// Self-cleaning invariant: g_mask and g_deg are zero at the start of every
// call (BSS zero-init at load; fill zeroes mask words it consumes; scan
// zeroes deg after reading).
__device__ unsigned int g_mask[MASK_WORDS];
__device__ int   g_deg[NN];
__device__ int   g_rowptr[NN + 1];
__device__ float g_dsqrtinv[NN];
__device__ int2  g_cv[2 * NE];     // packed {col, __float_as_int(val)}
__device__ float g_bufA[NN * ED];
__device__ float g_bufB[NN * ED];
__device__ int   g_is64;           // 1 if edge_index is int64

// ---------------- detect edge_index dtype ----------------
__global__ void lg_detect_kernel(const unsigned int* __restrict__ ei_raw) {
    if (threadIdx.x == 0) {
        int all_zero = 1;
        for (int k = 0; k < 128; ++k) {
            if (ei_raw[2 * k + 1] != 0u) { all_zero = 0; break; }
        }
        g_is64 = all_zero;
    }
}

// ---------------- mark edges (dedup via bitmask), count degrees ----------------
__global__ void lg_mark_kernel(const int* __restrict__ ei) {
    int t = blockIdx.x * blockDim.x + threadIdx.x;
    if (t >= 2 * NE) return;
    int e = t < NE ? t : t - NE;
    int u, v;
    if (g_is64) {
        u = ei[2 * e];
        v = ei[2 * (NE + e)];
    } else {
        u = ei[e];
        v = ei[NE + e];
    }
    int i, j;
    if (t < NE) { i = u; j = v; } else { i = v; j = u; }
    size_t bit = (size_t)i * NN + (size_t)j;
    unsigned int bm = 1u << (bit & 31);
    unsigned int old = atomicOr(&g_mask[bit >> 5], bm);
    if (!(old & bm)) atomicAdd(&g_deg[i], 1);
}

// ---------------- single-pass coarsened scan: deg -> rowptr, rsqrt, zero deg ----------------
__global__ void __launch_bounds__(1024) lg_scan_kernel() {
    __shared__ int warp_tot[32];
    const int PER = 12;                     // 1024 * 12 = 12288 >= 12000
    int t = threadIdx.x;
    int lane = t & 31, wid = t >> 5;
    int base = t * PER;
    int loc[PER];
    int sum = 0;
    #pragma unroll
    for (int k = 0; k < PER; k++) {
        int idx = base + k;
        int v = 0;
        if (idx < NN) {
            v = g_deg[idx];
            g_deg[idx] = 0;                 // self-clean for next call
            int d = v > 1 ? v : 1;
            g_dsqrtinv[idx] = rsqrtf((float)d);
        }
        sum += v;
        loc[k] = sum;                       // local inclusive
    }
    // warp inclusive scan of per-thread totals
    int ws = sum;
    #pragma unroll
    for (int s = 1; s < 32; s <<= 1) {
        int u = __shfl_up_sync(0xffffffffu, ws, s);
        if (lane >= s) ws += u;
    }
    if (lane == 31) warp_tot[wid] = ws;
    __syncthreads();
    if (wid == 0) {
        int v = warp_tot[lane];
        #pragma unroll
        for (int s = 1; s < 32; s <<= 1) {
            int u = __shfl_up_sync(0xffffffffu, v, s);
            if (lane >= s) v += u;
        }
        warp_tot[lane] = v;
    }
    __syncthreads();
    int excl = (ws - sum) + (wid > 0 ? warp_tot[wid - 1] : 0);
    #pragma unroll
    for (int k = 0; k < PER; k++) {
        int idx = base + k;
        if (idx < NN) g_rowptr[idx + 1] = excl + loc[k];
    }
    if (t == 0) g_rowptr[0] = 0;
}

// ---------------- fill packed CSR (warp per row, sorted cols), zero mask ----------------
__global__ void lg_fill_kernel() {
    int warp = (blockIdx.x * blockDim.x + threadIdx.x) >> 5;
    int lane = threadIdx.x & 31;
    if (warp >= NN) return;
    const int i = warp;
    unsigned int* row = g_mask + (size_t)i * WPR;
    int pos = g_rowptr[i];
    float di = g_dsqrtinv[i];
    for (int c = 0; c < WPR; c += 32) {
        int widx = c + lane;
        unsigned int w0 = (widx < WPR) ? row[widx] : 0u;
        unsigned int w = w0;
        int cnt = __popc(w);
        int inc = cnt;
        #pragma unroll
        for (int s = 1; s < 32; s <<= 1) {
            int t = __shfl_up_sync(0xffffffffu, inc, s);
            if (lane >= s) inc += t;
        }
        int total = __shfl_sync(0xffffffffu, inc, 31);
        int p = pos + inc - cnt;
        int jbase = widx * 32;
        while (w) {
            int b = __ffs(w) - 1;
            w &= w - 1;
            int j = jbase + b;
            int2 cv;
            cv.x = j;
            cv.y = __float_as_int(di * g_dsqrtinv[j]);
            g_cv[p] = cv;
            p++;
        }
        if (w0) row[widx] = 0u;            // self-clean (zero words stay zero)
        pos += total;
    }
}

// ---------------- init: concat embeddings into bufA and accumulator (d_out) ----------------
__global__ void lg_init_kernel(const float* __restrict__ uemb,
                               const float* __restrict__ iemb,
                               float* __restrict__ out) {
    int idx = blockIdx.x * blockDim.x + threadIdx.x;
    if (idx >= NN * ED) return;
    float v;
    if (idx < NU * ED) v = uemb[idx];
    else               v = iemb[idx - NU * ED];
    g_bufA[idx] = v;
    out[idx] = v;
}

// ---------------- SpMM: 16 dim-groups x 4 neighbor-slots, float4 gathers ----------------
// flip=0: read g_bufA, write g_bufB.  flip=1: read g_bufB, write g_bufA.
// Device-symbol pointers resolved in device code (host-side &g_bufX would be
// the host shadow; GB300 ATS makes that silently readable => zeros).
__global__ void __launch_bounds__(64) lg_spmm_kernel(int flip,
                                                     float* __restrict__ accum,
                                                     float scale) {
    const float* __restrict__ xin = flip ? g_bufB : g_bufA;
    float* __restrict__ xout      = flip ? g_bufA : g_bufB;
    __shared__ float4 sh[16];
    int i = blockIdx.x;
    int t = threadIdx.x;
    int lane16 = t & 15;          // dim group: dims [lane16*4, lane16*4+4)
    int slot   = t >> 4;          // neighbor slot 0..3
    int s = g_rowptr[i];
    int e = g_rowptr[i + 1];
    float4 acc = make_float4(0.f, 0.f, 0.f, 0.f);

    int p = s + slot;
    // 2-way unrolled: two neighbors in flight per thread (MLP=2 LDG.128)
    for (; p + 4 < e; p += 8) {
        int2 cv0 = g_cv[p];
        int2 cv1 = g_cv[p + 4];
        float w0 = __int_as_float(cv0.y);
        float w1 = __int_as_float(cv1.y);
        float4 x0 = *(const float4*)(xin + (size_t)cv0.x * ED + lane16 * 4);
        float4 x1 = *(const float4*)(xin + (size_t)cv1.x * ED + lane16 * 4);
        acc.x += w0 * x0.x + w1 * x1.x;
        acc.y += w0 * x0.y + w1 * x1.y;
        acc.z += w0 * x0.z + w1 * x1.z;
        acc.w += w0 * x0.w + w1 * x1.w;
    }
    if (p < e) {
        int2 cv = g_cv[p];
        float w = __int_as_float(cv.y);
        float4 xv = *(const float4*)(xin + (size_t)cv.x * ED + lane16 * 4);
        acc.x += w * xv.x;
        acc.y += w * xv.y;
        acc.z += w * xv.z;
        acc.w += w * xv.w;
    }

    // combine slot pairs within each warp (lanes t and t+16)
    acc.x += __shfl_down_sync(0xffffffffu, acc.x, 16);
    acc.y += __shfl_down_sync(0xffffffffu, acc.y, 16);
    acc.z += __shfl_down_sync(0xffffffffu, acc.z, 16);
    acc.w += __shfl_down_sync(0xffffffffu, acc.w, 16);
    if (t >= 32 && t < 48) sh[lane16] = acc;     // slots 2+3 partial
    __syncthreads();
    if (t < 16) {
        float4 o = sh[lane16];
        acc.x += o.x; acc.y += o.y; acc.z += o.z; acc.w += o.w;
        size_t off = (size_t)i * ED + lane16 * 4;
        *(float4*)(xout + off) = acc;
        float4 a = *(float4*)(accum + off);
        a.x = (a.x + acc.x) * scale;
        a.y = (a.y + acc.y) * scale;
        a.z = (a.z + acc.z) * scale;
        a.w = (a.w + acc.w) * scale;
        *(float4*)(accum + off) = a;
    }
}

extern "C" void kernel_launch(void* const* d_in, const int* in_sizes, int n_in,
                              void* d_out, int out_size) {
    const int*   edge_index = (const int*)d_in[0];   // (2, NE) int32 (or int64; detected)
    const float* user_emb   = (const float*)d_in[1]; // (NU, 64)
    const float* item_emb   = (const float*)d_in[2]; // (NI, 64)
    float* out = (float*)d_out;                       // (NN, 64) concat(users, items)

    (void)in_sizes; (void)n_in; (void)out_size;

    // 0. detect int32 vs int64 edge_index
    lg_detect_kernel<<<1, 32>>>((const unsigned int*)d_in[0]);
    // 1. mark both directions into bitmask (dedup), count degrees
    //    (mask & deg are guaranteed zero: BSS init + self-cleaning below)
    lg_mark_kernel<<<(2 * NE + 255) / 256, 256>>>(edge_index);
    // 2. rowptr prefix scan + rsqrt(deg); zeroes deg behind itself
    lg_scan_kernel<<<1, 1024>>>();
    // 3. deterministic packed CSR fill (sorted columns); zeroes mask behind itself
    lg_fill_kernel<<<(NN * 32 + 127) / 128, 128>>>();
    // 4. init X0 and accumulator (= layer-0 term)
    lg_init_kernel<<<(NN * ED + 255) / 256, 256>>>(user_emb, item_emb, out);
    // 5. three propagation layers; accumulate; mean(4 layers) on the last
    lg_spmm_kernel<<<NN, 64>>>(0, out, 1.0f);
    lg_spmm_kernel<<<NN, 64>>>(1, out, 1.0f);
    lg_spmm_kernel<<<NN, 64>>>(0, out, 0.25f);
}